// round 7
// baseline (speedup 1.0000x reference)
#include <cuda_runtime.h>

#define N_NODES 50000
#define N_EDGES 800000
#define F 128
#define BM_WORDS ((N_NODES + 31) / 32)

// ---- scratch (static device arrays; no allocation allowed) ----
__device__ unsigned g_bm1[BM_WORDS];          // S1 membership bitmap (6.25KB)
__device__ unsigned g_bm2[BM_WORDS];          // S2 membership bitmap
__device__ int   g_list1[N_NODES];
__device__ int   g_list2[512];
__device__ int   g_deg1[N_NODES];
__device__ int   g_deg2[N_NODES];
__device__ int2  g_elist1[N_EDGES];
__device__ int2  g_elist2[N_EDGES];
__device__ int   g_n1, g_n2, g_ne1, g_ne2;
__device__ float g_agg1[N_NODES * F];
__device__ float g_agg2[N_NODES * F];
__device__ float g_h1[N_NODES * F];
__device__ float g_h2[N_NODES * F];

__device__ __forceinline__ bool bm_test(const unsigned* bm, int n) {
    return (bm[n >> 5] >> (n & 31)) & 1u;
}

// ---------------- init: zero bitmaps+counters, insert S2 seeds ----------------
__global__ void __launch_bounds__(512) init_kernel(const int* __restrict__ states,
                                                   int n_states,
                                                   const int* __restrict__ actions) {
    int tid = threadIdx.x;
    for (int i = tid; i < BM_WORDS; i += 512) { g_bm1[i] = 0u; g_bm2[i] = 0u; }
    if (tid == 0) { g_n1 = 0; g_n2 = 0; g_ne1 = 0; g_ne2 = 0; }
    __syncthreads();
    for (int t = tid; t <= n_states; t += 512) {
        int node = (t < n_states) ? states[t] : actions[0];
        unsigned bit = 1u << (node & 31);
        unsigned old2 = atomicOr(&g_bm2[node >> 5], bit);
        if (!(old2 & bit)) {
            int p = atomicAdd(&g_n2, 1);
            g_list2[p] = node;
            g_deg2[node] = 0;
        }
        unsigned old1 = atomicOr(&g_bm1[node >> 5], bit);
        if (!(old1 & bit)) {
            int p = atomicAdd(&g_n1, 1);
            g_list1[p] = node;
            g_deg1[node] = 0;
        }
    }
}

// ---------------- pass A: zero agg2(list2); edges into S2 -> elist2, srcs -> S1 --
__global__ void __launch_bounds__(256) passA_kernel(const int* __restrict__ src,
                                                    const int* __restrict__ dst) {
    // zero agg2 rows for list2 (list2 final after init)
    {
        int n2 = g_n2;
        int nwarps = (gridDim.x * blockDim.x) >> 5;
        int warp = (blockIdx.x * blockDim.x + threadIdx.x) >> 5;
        int lane = threadIdx.x & 31;
        for (int w = warp; w < n2; w += nwarps)
            ((float4*)g_agg2)[g_list2[w] * 32 + lane] = make_float4(0.f, 0.f, 0.f, 0.f);
    }

    __shared__ int s_cnt, s_base;
    if (threadIdx.x == 0) s_cnt = 0;
    __syncthreads();

    int i4 = blockIdx.x * blockDim.x + threadIdx.x;
    int lane = threadIdx.x & 31;
    bool valid = (i4 * 4 < N_EDGES);
    int4 d4 = valid ? ((const int4*)dst)[i4] : make_int4(0, 0, 0, 0);
    int4 s4 = valid ? ((const int4*)src)[i4] : make_int4(0, 0, 0, 0);
    int dv[4] = {d4.x, d4.y, d4.z, d4.w};
    int sv[4] = {s4.x, s4.y, s4.z, s4.w};
    bool pass[4];
    int my = 0;
#pragma unroll
    for (int j = 0; j < 4; j++) {
        pass[j] = valid && bm_test(g_bm2, dv[j]);
        my += pass[j] ? 1 : 0;
    }
    int scan = my;
#pragma unroll
    for (int d = 1; d < 32; d <<= 1) {
        int t = __shfl_up_sync(0xffffffff, scan, d);
        if (lane >= d) scan += t;
    }
    int wtotal = __shfl_sync(0xffffffff, scan, 31);
    int wbase = 0;
    if (lane == 31 && wtotal > 0) wbase = atomicAdd(&s_cnt, wtotal);
    wbase = __shfl_sync(0xffffffff, wbase, 31);
    int my_off = wbase + scan - my;
    __syncthreads();
    if (threadIdx.x == 0) s_base = (s_cnt > 0) ? atomicAdd(&g_ne2, s_cnt) : 0;
    __syncthreads();
    int p = s_base + my_off;
#pragma unroll
    for (int j = 0; j < 4; j++) {
        if (pass[j]) {
            g_elist2[p++] = make_int2(sv[j], dv[j]);
            atomicAdd(&g_deg2[dv[j]], 1);
            unsigned bit = 1u << (sv[j] & 31);
            unsigned old = atomicOr(&g_bm1[sv[j] >> 5], bit);
            if (!(old & bit)) {
                int q = atomicAdd(&g_n1, 1);
                g_list1[q] = sv[j];
                g_deg1[sv[j]] = 0;
            }
        }
    }
}

// ---------------- pass B: zero agg1(list1); edges into S1 -> elist1 ----------------
__global__ void __launch_bounds__(256) passB_kernel(const int* __restrict__ src,
                                                    const int* __restrict__ dst) {
    // zero agg1 rows for list1 (list1 final after passA)
    {
        int n1 = g_n1;
        int nwarps = (gridDim.x * blockDim.x) >> 5;
        int warp = (blockIdx.x * blockDim.x + threadIdx.x) >> 5;
        int lane = threadIdx.x & 31;
        for (int w = warp; w < n1; w += nwarps)
            ((float4*)g_agg1)[g_list1[w] * 32 + lane] = make_float4(0.f, 0.f, 0.f, 0.f);
    }

    __shared__ int s_cnt, s_base;
    if (threadIdx.x == 0) s_cnt = 0;
    __syncthreads();

    int i4 = blockIdx.x * blockDim.x + threadIdx.x;
    int lane = threadIdx.x & 31;
    bool valid = (i4 * 4 < N_EDGES);
    int4 d4 = valid ? ((const int4*)dst)[i4] : make_int4(0, 0, 0, 0);
    int4 s4 = valid ? ((const int4*)src)[i4] : make_int4(0, 0, 0, 0);
    int dv[4] = {d4.x, d4.y, d4.z, d4.w};
    int sv[4] = {s4.x, s4.y, s4.z, s4.w};
    bool pass[4];
    int my = 0;
#pragma unroll
    for (int j = 0; j < 4; j++) {
        pass[j] = valid && bm_test(g_bm1, dv[j]);
        my += pass[j] ? 1 : 0;
    }
    int scan = my;
#pragma unroll
    for (int d = 1; d < 32; d <<= 1) {
        int t = __shfl_up_sync(0xffffffff, scan, d);
        if (lane >= d) scan += t;
    }
    int wtotal = __shfl_sync(0xffffffff, scan, 31);
    int wbase = 0;
    if (lane == 31 && wtotal > 0) wbase = atomicAdd(&s_cnt, wtotal);
    wbase = __shfl_sync(0xffffffff, wbase, 31);
    int my_off = wbase + scan - my;
    __syncthreads();
    if (threadIdx.x == 0) s_base = (s_cnt > 0) ? atomicAdd(&g_ne1, s_cnt) : 0;
    __syncthreads();
    int p = s_base + my_off;
#pragma unroll
    for (int j = 0; j < 4; j++) {
        if (pass[j]) {
            g_elist1[p++] = make_int2(sv[j], dv[j]);
            atomicAdd(&g_deg1[dv[j]], 1);
        }
    }
}

// ---------------- edge aggregation: warp per edge, vector red, 2-edge ILP ------
__global__ void edge_agg_kernel(const int2* __restrict__ elist, const int* __restrict__ ne_p,
                                const float* __restrict__ feat, float* __restrict__ agg) {
    int ne = *ne_p;
    int nwarps = (gridDim.x * blockDim.x) >> 5;
    int warp = (blockIdx.x * blockDim.x + threadIdx.x) >> 5;
    int lane = threadIdx.x & 31;
    int j = warp * 2;
    int stride = nwarps * 2;
    for (; j + 1 < ne; j += stride) {
        int2 e0 = elist[j];
        int2 e1 = elist[j + 1];
        float4 v0 = ((const float4*)feat)[e0.x * 32 + lane];
        float4 v1 = ((const float4*)feat)[e1.x * 32 + lane];
        float* a0 = &agg[e0.y * F + lane * 4];
        float* a1 = &agg[e1.y * F + lane * 4];
        asm volatile("red.global.add.v4.f32 [%0], {%1, %2, %3, %4};"
                     :: "l"(a0), "f"(v0.x), "f"(v0.y), "f"(v0.z), "f"(v0.w) : "memory");
        asm volatile("red.global.add.v4.f32 [%0], {%1, %2, %3, %4};"
                     :: "l"(a1), "f"(v1.x), "f"(v1.y), "f"(v1.z), "f"(v1.w) : "memory");
    }
    if (j < ne) {
        int2 e0 = elist[j];
        float4 v0 = ((const float4*)feat)[e0.x * 32 + lane];
        float* a0 = &agg[e0.y * F + lane * 4];
        asm volatile("red.global.add.v4.f32 [%0], {%1, %2, %3, %4};"
                     :: "l"(a0), "f"(v0.x), "f"(v0.y), "f"(v0.z), "f"(v0.w) : "memory");
    }
}

// ---------------- gathered fused SAGE GEMM (1/deg fused into A load) ----------
// out[node] = relu(feat[node]@Ws^T + (agg[node]/max(deg,1))@Wn^T + b)
// 256 threads, 32-row tile, 2x8 outputs/thread.
#define MT 32
#define KT 32

__global__ void __launch_bounds__(256) gemm_list_kernel(
    const int* __restrict__ list, const int* __restrict__ count_p,
    const float* __restrict__ feat, const float* __restrict__ agg,
    const int* __restrict__ deg,
    const float* __restrict__ Ws, const float* __restrict__ Wn,
    const float* __restrict__ bias, float* __restrict__ out)
{
    int count = *count_p;
    int ntiles = (count + MT - 1) / MT;
    if (blockIdx.x >= ntiles) return;

    __shared__ int   rows[MT];
    __shared__ float invs[MT];
    __shared__ float As[KT][MT + 4];
    __shared__ float Bs[KT][128 + 4];

    int tid = threadIdx.x;
    int m0  = blockIdx.x * MT;
    int r0  = (tid >> 4) * 2;     // 0..30 step 2
    int c0  = (tid & 15) * 8;     // 0..120 step 8

    if (tid < MT) {
        int nd = (m0 + tid < count) ? list[m0 + tid] : -1;
        rows[tid] = nd;
        invs[tid] = (nd >= 0) ? 1.0f / (float)max(deg[nd], 1) : 0.f;
    }
    __syncthreads();

    float acc[2][8];
#pragma unroll
    for (int m = 0; m < 2; m++)
#pragma unroll
        for (int n = 0; n < 8; n++) acc[m][n] = 0.f;

#pragma unroll 1
    for (int kt = 0; kt < 8; kt++) {
        const float* A = (kt < 4) ? feat : agg;
        const float* W = (kt < 4) ? Ws : Wn;
        int kb4 = (kt & 3) * 8;

        // A tile: 32 rows x 32 k = 256 float4, 1 per thread
        {
            int row = tid >> 3;
            int kq  = tid & 7;
            int nd  = rows[row];
            float4 a = make_float4(0.f, 0.f, 0.f, 0.f);
            if (nd >= 0) a = ((const float4*)A)[nd * 32 + kb4 + kq];
            float sc = (kt < 4) ? 1.0f : invs[row];
            As[kq * 4 + 0][row] = a.x * sc;
            As[kq * 4 + 1][row] = a.y * sc;
            As[kq * 4 + 2][row] = a.z * sc;
            As[kq * 4 + 3][row] = a.w * sc;
        }
        // W tile: 128 cols x 32 k = 1024 float4, 4 per thread
#pragma unroll
        for (int i = 0; i < 4; i++) {
            int v  = tid + 256 * i;
            int c  = v >> 3;
            int kq = v & 7;
            float4 w = ((const float4*)W)[c * 32 + kb4 + kq];
            Bs[kq * 4 + 0][c] = w.x;
            Bs[kq * 4 + 1][c] = w.y;
            Bs[kq * 4 + 2][c] = w.z;
            Bs[kq * 4 + 3][c] = w.w;
        }
        __syncthreads();

#pragma unroll
        for (int k = 0; k < KT; k++) {
            float2 a2 = *(const float2*)&As[k][r0];
            float4 b0 = *(const float4*)&Bs[k][c0];
            float4 b1 = *(const float4*)&Bs[k][c0 + 4];
            float am[2] = {a2.x, a2.y};
            float bn[8] = {b0.x, b0.y, b0.z, b0.w, b1.x, b1.y, b1.z, b1.w};
#pragma unroll
            for (int m = 0; m < 2; m++)
#pragma unroll
                for (int n = 0; n < 8; n++)
                    acc[m][n] += am[m] * bn[n];
        }
        __syncthreads();
    }

    float bv[8];
#pragma unroll
    for (int n = 0; n < 8; n++) bv[n] = bias[c0 + n];

#pragma unroll
    for (int m = 0; m < 2; m++) {
        int nd = rows[r0 + m];
        if (nd >= 0) {
            float4 o0, o1;
            o0.x = fmaxf(acc[m][0] + bv[0], 0.f);
            o0.y = fmaxf(acc[m][1] + bv[1], 0.f);
            o0.z = fmaxf(acc[m][2] + bv[2], 0.f);
            o0.w = fmaxf(acc[m][3] + bv[3], 0.f);
            o1.x = fmaxf(acc[m][4] + bv[4], 0.f);
            o1.y = fmaxf(acc[m][5] + bv[5], 0.f);
            o1.z = fmaxf(acc[m][6] + bv[6], 0.f);
            o1.w = fmaxf(acc[m][7] + bv[7], 0.f);
            ((float4*)out)[nd * 32 + (c0 >> 2)]     = o0;
            ((float4*)out)[nd * 32 + (c0 >> 2) + 1] = o1;
        }
    }
}

// ---------------- readout ----------------
__global__ void final_kernel(const int* __restrict__ states, int n_states,
                             const int* __restrict__ actions,
                             const float* __restrict__ Wfc,
                             const float* __restrict__ bfc,
                             float* __restrict__ out)
{
    int f = threadIdx.x;  // 128 threads
    float m = -1e30f;
#pragma unroll 4
    for (int s = 0; s < n_states; s++)
        m = fmaxf(m, g_h2[states[s] * F + f]);
    float av = g_h2[actions[0] * F + f];
    float p = m * Wfc[f] + av * Wfc[F + f];
    __shared__ float red[128];
    red[f] = p;
    __syncthreads();
    for (int d = 64; d > 0; d >>= 1) {
        if (f < d) red[f] += red[f + d];
        __syncthreads();
    }
    if (f == 0) out[0] = red[0] + bfc[0];
}

// ---------------- launch ----------------
extern "C" void kernel_launch(void* const* d_in, const int* in_sizes, int n_in,
                              void* d_out, int out_size) {
    const float* x      = (const float*)d_in[0];
    const int*   esrc   = (const int*)d_in[1];
    const int*   edst   = (const int*)d_in[2];
    const int*   states = (const int*)d_in[3];
    const int*   actions= (const int*)d_in[4];
    const float* W1s    = (const float*)d_in[5];
    const float* W1n    = (const float*)d_in[6];
    const float* b1     = (const float*)d_in[7];
    const float* W2s    = (const float*)d_in[8];
    const float* W2n    = (const float*)d_in[9];
    const float* b2     = (const float*)d_in[10];
    const float* Wfc    = (const float*)d_in[11];
    const float* bfc    = (const float*)d_in[12];
    float* out = (float*)d_out;
    int n_states = in_sizes[3];

    int *list1_p, *list2_p, *n1_p, *n2_p, *ne1_p, *ne2_p, *deg1_p, *deg2_p;
    int2 *elist1_p, *elist2_p;
    float *agg1_p, *agg2_p, *h1_p, *h2_p;
    cudaGetSymbolAddress((void**)&list1_p,  g_list1);
    cudaGetSymbolAddress((void**)&list2_p,  g_list2);
    cudaGetSymbolAddress((void**)&n1_p,     g_n1);
    cudaGetSymbolAddress((void**)&n2_p,     g_n2);
    cudaGetSymbolAddress((void**)&ne1_p,    g_ne1);
    cudaGetSymbolAddress((void**)&ne2_p,    g_ne2);
    cudaGetSymbolAddress((void**)&deg1_p,   g_deg1);
    cudaGetSymbolAddress((void**)&deg2_p,   g_deg2);
    cudaGetSymbolAddress((void**)&elist1_p, g_elist1);
    cudaGetSymbolAddress((void**)&elist2_p, g_elist2);
    cudaGetSymbolAddress((void**)&agg1_p,   g_agg1);
    cudaGetSymbolAddress((void**)&agg2_p,   g_agg2);
    cudaGetSymbolAddress((void**)&h1_p,     g_h1);
    cudaGetSymbolAddress((void**)&h2_p,     g_h2);

    const int QUADS = N_EDGES / 4;                 // 200000
    const int pass_blocks = (QUADS + 255) / 256;   // 782

    // frontier construction (+fused agg zeroing)
    init_kernel<<<1, 512>>>(states, n_states, actions);
    passA_kernel<<<pass_blocks, 256>>>(esrc, edst);
    passB_kernel<<<pass_blocks, 256>>>(esrc, edst);

    // layer 1 (nodes in S1)
    edge_agg_kernel<<<1024, 256>>>(elist1_p, ne1_p, x, agg1_p);
    gemm_list_kernel<<<(N_NODES + MT - 1) / MT, 256>>>(list1_p, n1_p, x, agg1_p, deg1_p,
                                                       W1s, W1n, b1, h1_p);

    // layer 2 (nodes in S2)
    edge_agg_kernel<<<1024, 256>>>(elist2_p, ne2_p, h1_p, agg2_p);
    gemm_list_kernel<<<9, 256>>>(list2_p, n2_p, h1_p, agg2_p, deg2_p,
                                 W2s, W2n, b2, h2_p);

    // readout
    final_kernel<<<1, 128>>>(states, n_states, actions, Wfc, bfc, out);
}

// round 8
// speedup vs baseline: 1.6293x; 1.6293x over previous
#include <cuda_runtime.h>

#define N_NODES 50000
#define N_EDGES 800000
#define F 128
#define BM_WORDS ((N_NODES + 31) / 32)

// ---- scratch (static device arrays; no allocation allowed) ----
__device__ unsigned g_bm1[BM_WORDS];          // S1 membership bitmap (6.25KB)
__device__ unsigned g_bm2[BM_WORDS];          // S2 membership bitmap
__device__ int   g_list1[N_NODES];
__device__ int   g_list2[512];
__device__ int   g_deg1[N_NODES];
__device__ int   g_deg2[N_NODES];
__device__ int2  g_elist1[N_EDGES];
__device__ int2  g_elist2[N_EDGES];
__device__ int   g_n1, g_n2, g_ne1, g_ne2;
__device__ float g_agg1[N_NODES * F];
__device__ float g_agg2[N_NODES * F];
__device__ float g_h1[N_NODES * F];
__device__ float g_h2[N_NODES * F];

__device__ __forceinline__ bool bm_test(const unsigned* bm, int n) {
    return (bm[n >> 5] >> (n & 31)) & 1u;
}

// ---------------- init: zero bitmaps+counters, insert S2 seeds (1 block) -------
__global__ void __launch_bounds__(512) init_kernel(const int* __restrict__ states,
                                                   int n_states,
                                                   const int* __restrict__ actions) {
    int tid = threadIdx.x;
    for (int i = tid; i < BM_WORDS; i += 512) { g_bm1[i] = 0u; g_bm2[i] = 0u; }
    if (tid == 0) { g_n1 = 0; g_n2 = 0; g_ne1 = 0; g_ne2 = 0; }
    __syncthreads();
    for (int t = tid; t <= n_states; t += 512) {
        int node = (t < n_states) ? states[t] : actions[0];
        unsigned bit = 1u << (node & 31);
        unsigned old2 = atomicOr(&g_bm2[node >> 5], bit);
        if (!(old2 & bit)) {
            int p = atomicAdd(&g_n2, 1);
            g_list2[p] = node;
            g_deg2[node] = 0;
        }
        unsigned old1 = atomicOr(&g_bm1[node >> 5], bit);
        if (!(old1 & bit)) {
            int p = atomicAdd(&g_n1, 1);
            g_list1[p] = node;
            g_deg1[node] = 0;
        }
    }
}

// ---------------- pass A: zero agg2(list2); edges into S2 -> elist2, srcs -> S1 --
__global__ void __launch_bounds__(256) passA_kernel(const int* __restrict__ src,
                                                    const int* __restrict__ dst) {
    // zero agg2 rows for list2 (list2 final after init; agg2 consumed 3 launches later)
    {
        int n2 = g_n2;
        int nwarps = (gridDim.x * blockDim.x) >> 5;
        int warp = (blockIdx.x * blockDim.x + threadIdx.x) >> 5;
        int lane = threadIdx.x & 31;
        for (int w = warp; w < n2; w += nwarps)
            ((float4*)g_agg2)[g_list2[w] * 32 + lane] = make_float4(0.f, 0.f, 0.f, 0.f);
    }

    __shared__ int s_cnt, s_base;
    if (threadIdx.x == 0) s_cnt = 0;
    __syncthreads();

    int i4 = blockIdx.x * blockDim.x + threadIdx.x;
    int lane = threadIdx.x & 31;
    bool valid = (i4 * 4 < N_EDGES);
    int4 d4 = valid ? ((const int4*)dst)[i4] : make_int4(0, 0, 0, 0);
    int4 s4 = valid ? ((const int4*)src)[i4] : make_int4(0, 0, 0, 0);
    int dv[4] = {d4.x, d4.y, d4.z, d4.w};
    int sv[4] = {s4.x, s4.y, s4.z, s4.w};
    bool pass[4];
    int my = 0;
#pragma unroll
    for (int j = 0; j < 4; j++) {
        pass[j] = valid && bm_test(g_bm2, dv[j]);
        my += pass[j] ? 1 : 0;
    }
    int scan = my;
#pragma unroll
    for (int d = 1; d < 32; d <<= 1) {
        int t = __shfl_up_sync(0xffffffff, scan, d);
        if (lane >= d) scan += t;
    }
    int wtotal = __shfl_sync(0xffffffff, scan, 31);
    int wbase = 0;
    if (lane == 31 && wtotal > 0) wbase = atomicAdd(&s_cnt, wtotal);
    wbase = __shfl_sync(0xffffffff, wbase, 31);
    int my_off = wbase + scan - my;
    __syncthreads();
    if (threadIdx.x == 0) s_base = (s_cnt > 0) ? atomicAdd(&g_ne2, s_cnt) : 0;
    __syncthreads();
    int p = s_base + my_off;
#pragma unroll
    for (int j = 0; j < 4; j++) {
        if (pass[j]) {
            g_elist2[p++] = make_int2(sv[j], dv[j]);
            atomicAdd(&g_deg2[dv[j]], 1);
            unsigned bit = 1u << (sv[j] & 31);
            unsigned old = atomicOr(&g_bm1[sv[j] >> 5], bit);
            if (!(old & bit)) {
                int q = atomicAdd(&g_n1, 1);
                g_list1[q] = sv[j];
                g_deg1[sv[j]] = 0;
            }
        }
    }
}

// ---------------- pass B: zero agg1(list1); edges into S1 -> elist1 ------------
__global__ void __launch_bounds__(256) passB_kernel(const int* __restrict__ src,
                                                    const int* __restrict__ dst) {
    // zero agg1 rows for list1 (list1 final after passA; agg1 consumed next launch)
    {
        int n1 = g_n1;
        int nwarps = (gridDim.x * blockDim.x) >> 5;
        int warp = (blockIdx.x * blockDim.x + threadIdx.x) >> 5;
        int lane = threadIdx.x & 31;
        for (int w = warp; w < n1; w += nwarps)
            ((float4*)g_agg1)[g_list1[w] * 32 + lane] = make_float4(0.f, 0.f, 0.f, 0.f);
    }

    __shared__ int s_cnt, s_base;
    if (threadIdx.x == 0) s_cnt = 0;
    __syncthreads();

    int i4 = blockIdx.x * blockDim.x + threadIdx.x;
    int lane = threadIdx.x & 31;
    bool valid = (i4 * 4 < N_EDGES);
    int4 d4 = valid ? ((const int4*)dst)[i4] : make_int4(0, 0, 0, 0);
    int4 s4 = valid ? ((const int4*)src)[i4] : make_int4(0, 0, 0, 0);
    int dv[4] = {d4.x, d4.y, d4.z, d4.w};
    int sv[4] = {s4.x, s4.y, s4.z, s4.w};
    bool pass[4];
    int my = 0;
#pragma unroll
    for (int j = 0; j < 4; j++) {
        pass[j] = valid && bm_test(g_bm1, dv[j]);
        my += pass[j] ? 1 : 0;
    }
    int scan = my;
#pragma unroll
    for (int d = 1; d < 32; d <<= 1) {
        int t = __shfl_up_sync(0xffffffff, scan, d);
        if (lane >= d) scan += t;
    }
    int wtotal = __shfl_sync(0xffffffff, scan, 31);
    int wbase = 0;
    if (lane == 31 && wtotal > 0) wbase = atomicAdd(&s_cnt, wtotal);
    wbase = __shfl_sync(0xffffffff, wbase, 31);
    int my_off = wbase + scan - my;
    __syncthreads();
    if (threadIdx.x == 0) s_base = (s_cnt > 0) ? atomicAdd(&g_ne1, s_cnt) : 0;
    __syncthreads();
    int p = s_base + my_off;
#pragma unroll
    for (int j = 0; j < 4; j++) {
        if (pass[j]) {
            g_elist1[p++] = make_int2(sv[j], dv[j]);
            atomicAdd(&g_deg1[dv[j]], 1);
        }
    }
}

// ---------------- edge aggregation: one warp per edge, vector red (PROVEN) -----
__global__ void edge_agg_kernel(const int2* __restrict__ elist, const int* __restrict__ ne_p,
                                const float* __restrict__ feat, float* __restrict__ agg) {
    int ne = *ne_p;
    int nwarps = (gridDim.x * blockDim.x) >> 5;
    int warp = (blockIdx.x * blockDim.x + threadIdx.x) >> 5;
    int lane = threadIdx.x & 31;
    for (int j = warp; j < ne; j += nwarps) {
        int2 e = elist[j];
        float4 v = ((const float4*)feat)[e.x * 32 + lane];
        float* a = &agg[e.y * F + lane * 4];
        asm volatile("red.global.add.v4.f32 [%0], {%1, %2, %3, %4};"
                     :: "l"(a), "f"(v.x), "f"(v.y), "f"(v.z), "f"(v.w) : "memory");
    }
}

// ---------------- gathered fused SAGE GEMM (PROVEN 128-thread 4x8 form) --------
// out[node] = relu(feat[node]@Ws^T + (agg[node]/max(deg,1))@Wn^T + b)
#define MT 32
#define KT 32

__global__ void __launch_bounds__(128) gemm_list_kernel(
    const int* __restrict__ list, const int* __restrict__ count_p,
    const float* __restrict__ feat, const float* __restrict__ agg,
    const int* __restrict__ deg,
    const float* __restrict__ Ws, const float* __restrict__ Wn,
    const float* __restrict__ bias, float* __restrict__ out)
{
    int count = *count_p;
    int ntiles = (count + MT - 1) / MT;
    if (blockIdx.x >= ntiles) return;

    __shared__ int   rows[MT];
    __shared__ float invs[MT];
    __shared__ float As[KT][MT + 4];
    __shared__ float Bs[KT][128 + 4];

    int tid = threadIdx.x;
    int m0  = blockIdx.x * MT;
    int r0  = (tid >> 4) * 4;     // 0..28 step 4
    int c0  = (tid & 15) * 8;     // 0..120 step 8

    if (tid < MT) {
        int nd = (m0 + tid < count) ? list[m0 + tid] : -1;
        rows[tid] = nd;
        invs[tid] = (nd >= 0) ? 1.0f / (float)max(deg[nd], 1) : 0.f;
    }
    __syncthreads();

    float acc[4][8];
#pragma unroll
    for (int m = 0; m < 4; m++)
#pragma unroll
        for (int n = 0; n < 8; n++) acc[m][n] = 0.f;

#pragma unroll 1
    for (int kt = 0; kt < 8; kt++) {
        const float* A = (kt < 4) ? feat : agg;
        const float* W = (kt < 4) ? Ws : Wn;
        int kb4 = (kt & 3) * 8;

        // A tile: 32 rows x 32 k = 256 float4, 2 per thread (scaled if agg half)
#pragma unroll
        for (int i = 0; i < 2; i++) {
            int v   = tid + 128 * i;
            int row = v >> 3;
            int kq  = v & 7;
            int nd  = rows[row];
            float4 a = make_float4(0.f, 0.f, 0.f, 0.f);
            if (nd >= 0) a = ((const float4*)A)[nd * 32 + kb4 + kq];
            float sc = (kt < 4) ? 1.0f : invs[row];
            As[kq * 4 + 0][row] = a.x * sc;
            As[kq * 4 + 1][row] = a.y * sc;
            As[kq * 4 + 2][row] = a.z * sc;
            As[kq * 4 + 3][row] = a.w * sc;
        }
        // W tile: 128 cols x 32 k = 1024 float4, 8 per thread
#pragma unroll
        for (int i = 0; i < 8; i++) {
            int v  = tid + 128 * i;
            int c  = v >> 3;
            int kq = v & 7;
            float4 w = ((const float4*)W)[c * 32 + kb4 + kq];
            Bs[kq * 4 + 0][c] = w.x;
            Bs[kq * 4 + 1][c] = w.y;
            Bs[kq * 4 + 2][c] = w.z;
            Bs[kq * 4 + 3][c] = w.w;
        }
        __syncthreads();

#pragma unroll
        for (int k = 0; k < KT; k++) {
            float4 a4 = *(const float4*)&As[k][r0];
            float4 b0 = *(const float4*)&Bs[k][c0];
            float4 b1 = *(const float4*)&Bs[k][c0 + 4];
            float am[4] = {a4.x, a4.y, a4.z, a4.w};
            float bn[8] = {b0.x, b0.y, b0.z, b0.w, b1.x, b1.y, b1.z, b1.w};
#pragma unroll
            for (int m = 0; m < 4; m++)
#pragma unroll
                for (int n = 0; n < 8; n++)
                    acc[m][n] += am[m] * bn[n];
        }
        __syncthreads();
    }

    float bv[8];
#pragma unroll
    for (int n = 0; n < 8; n++) bv[n] = bias[c0 + n];

#pragma unroll
    for (int m = 0; m < 4; m++) {
        int nd = rows[r0 + m];
        if (nd >= 0) {
            float4 o0, o1;
            o0.x = fmaxf(acc[m][0] + bv[0], 0.f);
            o0.y = fmaxf(acc[m][1] + bv[1], 0.f);
            o0.z = fmaxf(acc[m][2] + bv[2], 0.f);
            o0.w = fmaxf(acc[m][3] + bv[3], 0.f);
            o1.x = fmaxf(acc[m][4] + bv[4], 0.f);
            o1.y = fmaxf(acc[m][5] + bv[5], 0.f);
            o1.z = fmaxf(acc[m][6] + bv[6], 0.f);
            o1.w = fmaxf(acc[m][7] + bv[7], 0.f);
            ((float4*)out)[nd * 32 + (c0 >> 2)]     = o0;
            ((float4*)out)[nd * 32 + (c0 >> 2) + 1] = o1;
        }
    }
}

// ---------------- readout ----------------
__global__ void final_kernel(const int* __restrict__ states, int n_states,
                             const int* __restrict__ actions,
                             const float* __restrict__ Wfc,
                             const float* __restrict__ bfc,
                             float* __restrict__ out)
{
    int f = threadIdx.x;  // 128 threads
    float m = -1e30f;
#pragma unroll 4
    for (int s = 0; s < n_states; s++)
        m = fmaxf(m, g_h2[states[s] * F + f]);
    float av = g_h2[actions[0] * F + f];
    float p = m * Wfc[f] + av * Wfc[F + f];
    __shared__ float red[128];
    red[f] = p;
    __syncthreads();
    for (int d = 64; d > 0; d >>= 1) {
        if (f < d) red[f] += red[f + d];
        __syncthreads();
    }
    if (f == 0) out[0] = red[0] + bfc[0];
}

// ---------------- launch ----------------
extern "C" void kernel_launch(void* const* d_in, const int* in_sizes, int n_in,
                              void* d_out, int out_size) {
    const float* x      = (const float*)d_in[0];
    const int*   esrc   = (const int*)d_in[1];
    const int*   edst   = (const int*)d_in[2];
    const int*   states = (const int*)d_in[3];
    const int*   actions= (const int*)d_in[4];
    const float* W1s    = (const float*)d_in[5];
    const float* W1n    = (const float*)d_in[6];
    const float* b1     = (const float*)d_in[7];
    const float* W2s    = (const float*)d_in[8];
    const float* W2n    = (const float*)d_in[9];
    const float* b2     = (const float*)d_in[10];
    const float* Wfc    = (const float*)d_in[11];
    const float* bfc    = (const float*)d_in[12];
    float* out = (float*)d_out;
    int n_states = in_sizes[3];

    int *list1_p, *list2_p, *n1_p, *n2_p, *ne1_p, *ne2_p, *deg1_p, *deg2_p;
    int2 *elist1_p, *elist2_p;
    float *agg1_p, *agg2_p, *h1_p, *h2_p;
    cudaGetSymbolAddress((void**)&list1_p,  g_list1);
    cudaGetSymbolAddress((void**)&list2_p,  g_list2);
    cudaGetSymbolAddress((void**)&n1_p,     g_n1);
    cudaGetSymbolAddress((void**)&n2_p,     g_n2);
    cudaGetSymbolAddress((void**)&ne1_p,    g_ne1);
    cudaGetSymbolAddress((void**)&ne2_p,    g_ne2);
    cudaGetSymbolAddress((void**)&deg1_p,   g_deg1);
    cudaGetSymbolAddress((void**)&deg2_p,   g_deg2);
    cudaGetSymbolAddress((void**)&elist1_p, g_elist1);
    cudaGetSymbolAddress((void**)&elist2_p, g_elist2);
    cudaGetSymbolAddress((void**)&agg1_p,   g_agg1);
    cudaGetSymbolAddress((void**)&agg2_p,   g_agg2);
    cudaGetSymbolAddress((void**)&h1_p,     g_h1);
    cudaGetSymbolAddress((void**)&h2_p,     g_h2);

    const int QUADS = N_EDGES / 4;                 // 200000
    const int pass_blocks = (QUADS + 255) / 256;   // 782

    // frontier construction (+fused agg zeroing)
    init_kernel<<<1, 512>>>(states, n_states, actions);
    passA_kernel<<<pass_blocks, 256>>>(esrc, edst);
    passB_kernel<<<pass_blocks, 256>>>(esrc, edst);

    // layer 1 (nodes in S1)
    edge_agg_kernel<<<1024, 256>>>(elist1_p, ne1_p, x, agg1_p);
    gemm_list_kernel<<<(N_NODES + MT - 1) / MT, 128>>>(list1_p, n1_p, x, agg1_p, deg1_p,
                                                       W1s, W1n, b1, h1_p);

    // layer 2 (nodes in S2)
    edge_agg_kernel<<<1024, 256>>>(elist2_p, ne2_p, h1_p, agg2_p);
    gemm_list_kernel<<<9, 128>>>(list2_p, n2_p, h1_p, agg2_p, deg2_p,
                                 W2s, W2n, b2, h2_p);

    // readout
    final_kernel<<<1, 128>>>(states, n_states, actions, Wfc, bfc, out);
}